// round 4
// baseline (speedup 1.0000x reference)
#include <cuda_runtime.h>
#include <cstdint>

// Problem constants
#define T_TOK 4096      // total tokens (B*S)
#define DDIM  4096      // D_IN == D_OUT
#define NE    8         // experts

// GEMM tile config: CTA tile 256x128, 8 warps, warp tile 64x64
#define BM 256
#define BN 128
#define BK 32
#define NSTAGE 3
#define ALD 36          // BK + 4 pad (floats) -> conflict-free fragment LDS
#define GEMM_THREADS 256

// -------- device-global scratch (no allocation allowed) --------
__device__ int   g_cnt[NE];
__device__ float g_importance[NE];
__device__ int   g_tok[NE * T_TOK];
__device__ float g_scale[NE * T_TOK];
__device__ float g_xc[(size_t)T_TOK * DDIM];        // 64 MB  tf32-rounded x
__device__ float g_wc[(size_t)NE * DDIM * DDIM];    // 512 MB tf32-rounded W

// ---------------------------------------------------------------
__device__ __forceinline__ uint32_t f2tf(float f) {
    uint32_t r;
    asm volatile("cvt.rna.tf32.f32 %0, %1;\n" : "=r"(r) : "f"(f));
    return r;
}

__global__ void reset_kernel() {
    int i = threadIdx.x;
    if (i < NE) { g_cnt[i] = 0; g_importance[i] = 0.f; }
}

// One block (128 threads) per token: logits = tanh(x @ gw1^T) @ gw2^T, top-2,
// softmax, append to per-expert lists. Also writes tf32-rounded x to g_xc.
__global__ void gate_kernel(const float4* __restrict__ x4,
                            const float4* __restrict__ gw1_4,
                            const float* __restrict__ gw2) {
    int t = blockIdx.x;
    const float4* xr = x4 + (size_t)t * (DDIM / 4);
    float4* xc = (float4*)g_xc + (size_t)t * (DDIM / 4);

    float acc[NE];
#pragma unroll
    for (int e = 0; e < NE; e++) acc[e] = 0.f;

    for (int i = threadIdx.x; i < DDIM / 4; i += 128) {
        float4 v = xr[i];
        // fused tf32-rounding store (gate math uses original fp32 v)
        float4 r;
        r.x = __uint_as_float(f2tf(v.x));
        r.y = __uint_as_float(f2tf(v.y));
        r.z = __uint_as_float(f2tf(v.z));
        r.w = __uint_as_float(f2tf(v.w));
        xc[i] = r;
#pragma unroll
        for (int e = 0; e < NE; e++) {
            float4 w = gw1_4[e * (DDIM / 4) + i];
            acc[e] += v.x * w.x + v.y * w.y + v.z * w.z + v.w * w.w;
        }
    }
#pragma unroll
    for (int e = 0; e < NE; e++) {
#pragma unroll
        for (int o = 16; o > 0; o >>= 1)
            acc[e] += __shfl_xor_sync(0xffffffffu, acc[e], o);
    }
    __shared__ float part[NE][4];
    __shared__ float hs[NE];
    __shared__ float ls[NE];
    int lane = threadIdx.x & 31, warp = threadIdx.x >> 5;
    if (lane == 0) {
#pragma unroll
        for (int e = 0; e < NE; e++) part[e][warp] = acc[e];
    }
    __syncthreads();
    if (threadIdx.x < NE) {
        int e = threadIdx.x;
        hs[e] = tanhf(part[e][0] + part[e][1] + part[e][2] + part[e][3]);
    }
    __syncthreads();
    if (threadIdx.x < NE) {
        int j = threadIdx.x;
        float l = 0.f;
#pragma unroll
        for (int e = 0; e < NE; e++) l += gw2[j * NE + e] * hs[e];
        ls[j] = l;
    }
    __syncthreads();
    if (threadIdx.x == 0) {
        int i0 = 0; float v0 = ls[0];
        for (int j = 1; j < NE; j++) if (ls[j] > v0) { v0 = ls[j]; i0 = j; }
        int i1 = -1; float v1 = -3.4e38f;
        for (int j = 0; j < NE; j++) if (j != i0 && ls[j] > v1) { v1 = ls[j]; i1 = j; }
        float z  = expf(v1 - v0);
        float s0 = 1.f / (1.f + z);
        float s1 = z * s0;
        int p0 = atomicAdd(&g_cnt[i0], 1);
        g_tok[i0 * T_TOK + p0]   = t;
        g_scale[i0 * T_TOK + p0] = s0;
        int p1 = atomicAdd(&g_cnt[i1], 1);
        g_tok[i1 * T_TOK + p1]   = t;
        g_scale[i1 * T_TOK + p1] = s1;
        atomicAdd(&g_importance[i0], s0);
        atomicAdd(&g_importance[i1], s1);
    }
}

__global__ void loss_kernel(float* __restrict__ out) {
    float v[NE], w[NE];
    float m1 = 0.f, m2 = 0.f;
#pragma unroll
    for (int e = 0; e < NE; e++) {
        v[e] = g_importance[e];
        w[e] = (float)g_cnt[e];
        m1 += v[e]; m2 += w[e];
    }
    m1 *= (1.f / NE); m2 *= (1.f / NE);
    float var1 = 0.f, var2 = 0.f;
#pragma unroll
    for (int e = 0; e < NE; e++) {
        float d1 = v[e] - m1; var1 += d1 * d1;
        float d2 = w[e] - m2; var2 += d2 * d2;
    }
    var1 *= (1.f / (NE - 1)); var2 *= (1.f / (NE - 1));
    out[0] = 0.01f * (var1 / (m1 * m1 + 1e-10f) + var2 / (m2 * m2 + 1e-10f));
}

// ---------------- W pre-convert (rna fp32 -> tf32-precision fp32) ----------------
__global__ void cvt_w_kernel(const float4* __restrict__ src) {
    int i = blockIdx.x * 256 + threadIdx.x;
    const int n4 = (int)((size_t)NE * DDIM * (DDIM / 4));
    if (i < n4) {
        float4 v = src[i];
        v.x = __uint_as_float(f2tf(v.x));
        v.y = __uint_as_float(f2tf(v.y));
        v.z = __uint_as_float(f2tf(v.z));
        v.w = __uint_as_float(f2tf(v.w));
        ((float4*)g_wc)[i] = v;
    }
}

// ---------------------------------------------------------------
__device__ __forceinline__ void mma_tf32(float* c, const uint32_t* a, const uint32_t* b) {
    asm volatile(
        "mma.sync.aligned.m16n8k8.row.col.f32.tf32.tf32.f32 "
        "{%0,%1,%2,%3}, {%4,%5,%6,%7}, {%8,%9}, {%0,%1,%2,%3};\n"
        : "+f"(c[0]), "+f"(c[1]), "+f"(c[2]), "+f"(c[3])
        : "r"(a[0]), "r"(a[1]), "r"(a[2]), "r"(a[3]), "r"(b[0]), "r"(b[1]));
}
__device__ __forceinline__ void cp_async16(void* smem_dst, const void* gsrc) {
    uint32_t s = (uint32_t)__cvta_generic_to_shared(smem_dst);
    asm volatile("cp.async.cg.shared.global [%0], [%1], 16;\n" :: "r"(s), "l"(gsrc) : "memory");
}

// Grouped expert GEMM on tf32-rounded operands; epilogue scatter-add.
// CTA tile 256x128, warp tile 64x64 (warps: 4 along M, 2 along N).
__global__ void __launch_bounds__(GEMM_THREADS, 1)
moe_gemm(const float* __restrict__ bias, float* __restrict__ y) {
    int e   = blockIdx.z;
    int cnt = g_cnt[e];
    int m0  = blockIdx.x * BM;
    if (m0 >= cnt) return;
    int n0  = blockIdx.y * BN;

    extern __shared__ float smem[];
    float* As     = smem;                                   // NSTAGE*BM*ALD
    float* Bs     = As + NSTAGE * BM * ALD;                 // NSTAGE*BN*ALD
    float* sBias  = Bs + NSTAGE * BN * ALD;                 // BN
    float* sScale = sBias + BN;                             // BM
    int*   sTok   = (int*)(sScale + BM);                    // BM

    int tid = threadIdx.x;
    {
        int m = m0 + tid;
        bool valid = m < cnt;
        sTok[tid]   = valid ? g_tok[e * T_TOK + m]   : 0;
        sScale[tid] = valid ? g_scale[e * T_TOK + m] : 0.f;
        int m2 = m0 + 128 + tid;          // second half handled by low 128 threads? no:
    }
    // second half of rows (tid covers 0..255, BM=256 -> one pass):
    // (BM == GEMM_THREADS so the loop above covers all rows)
    if (tid < BN) sBias[tid] = bias[e * DDIM + n0 + tid];
    __syncthreads();

    // per-thread load slots: A rows r_a + it*32 (it=0..7), B rows r_a + it*32 (it=0..3)
    int r_a = tid >> 3, c_a = tid & 7;
    const float* a_src[8];
#pragma unroll
    for (int it = 0; it < 8; it++) {
        int r = r_a + it * 32;
        a_src[it] = g_xc + (size_t)sTok[r] * DDIM + c_a * 4;
    }
    const float* b_base = g_wc + ((size_t)e * DDIM + n0 + r_a) * DDIM + c_a * 4;

    auto load_stage = [&](int stage, int kt) {
        int kk = kt * BK;
        float* as = As + stage * (BM * ALD);
        float* bs = Bs + stage * (BN * ALD);
#pragma unroll
        for (int it = 0; it < 8; it++) {
            int r = r_a + it * 32;
            cp_async16(as + r * ALD + c_a * 4, a_src[it] + kk);
        }
#pragma unroll
        for (int it = 0; it < 4; it++) {
            int r = r_a + it * 32;
            cp_async16(bs + r * ALD + c_a * 4, b_base + (size_t)(it * 32) * DDIM + kk);
        }
        asm volatile("cp.async.commit_group;\n" ::: "memory");
    };

    const int KT = DDIM / BK;  // 128
    load_stage(0, 0);
    load_stage(1, 1);

    int warp = tid >> 5;
    int wm   = warp & 3;        // 4 warps along M -> 64 rows each
    int wn   = warp >> 2;       // 2 warps along N -> 64 cols each
    int lane = tid & 31;
    int gid  = lane >> 2;       // 0..7
    int tg   = lane & 3;        // 0..3

    float c[4][8][4];
#pragma unroll
    for (int mi = 0; mi < 4; mi++)
#pragma unroll
        for (int ni = 0; ni < 8; ni++)
#pragma unroll
            for (int j = 0; j < 4; j++) c[mi][ni][j] = 0.f;

    for (int i = 0; i < KT; i++) {
        if (i < KT - 1) {
            asm volatile("cp.async.wait_group 1;\n" ::: "memory");
        } else {
            asm volatile("cp.async.wait_group 0;\n" ::: "memory");
        }
        __syncthreads();
        if (i + 2 < KT) load_stage((i + 2) % NSTAGE, i + 2);

        const uint32_t* as = (const uint32_t*)(As + (i % NSTAGE) * (BM * ALD)) + (wm * 64) * ALD;
        const uint32_t* bs = (const uint32_t*)(Bs + (i % NSTAGE) * (BN * ALD)) + (wn * 64) * ALD;

#pragma unroll
        for (int ks = 0; ks < BK / 8; ks++) {
            uint32_t a[4][4], b[8][2];
#pragma unroll
            for (int mi = 0; mi < 4; mi++) {
                const uint32_t* ap = as + (mi * 16 + gid) * ALD + ks * 8 + tg;
                a[mi][0] = ap[0];
                a[mi][1] = ap[8 * ALD];
                a[mi][2] = ap[4];
                a[mi][3] = ap[8 * ALD + 4];
            }
#pragma unroll
            for (int ni = 0; ni < 8; ni++) {
                const uint32_t* bp = bs + (ni * 8 + gid) * ALD + ks * 8 + tg;
                b[ni][0] = bp[0];
                b[ni][1] = bp[4];
            }
#pragma unroll
            for (int mi = 0; mi < 4; mi++)
#pragma unroll
                for (int ni = 0; ni < 8; ni++)
                    mma_tf32(c[mi][ni], a[mi], b[ni]);
        }
    }

    // epilogue: scatter-add
#pragma unroll
    for (int mi = 0; mi < 4; mi++) {
#pragma unroll
        for (int half = 0; half < 2; half++) {
            int r = wm * 64 + mi * 16 + gid + half * 8;
            if (m0 + r >= cnt) continue;
            int   tok = sTok[r];
            float sc  = sScale[r];
            float* yr = y + (size_t)tok * DDIM + n0;
#pragma unroll
            for (int ni = 0; ni < 8; ni++) {
                int col = wn * 64 + ni * 8 + tg * 2;
                float v0 = sc * (c[mi][ni][half * 2 + 0] + sBias[col]);
                float v1 = sc * (c[mi][ni][half * 2 + 1] + sBias[col + 1]);
                atomicAdd(&yr[col],     v0);
                atomicAdd(&yr[col + 1], v1);
            }
        }
    }
}

// ---------------------------------------------------------------
extern "C" void kernel_launch(void* const* d_in, const int* in_sizes, int n_in,
                              void* d_out, int out_size) {
    const float* x   = (const float*)d_in[0];
    const float* gw1 = (const float*)d_in[1];
    const float* gw2 = (const float*)d_in[2];
    const float* ew  = (const float*)d_in[3];
    const float* eb  = (const float*)d_in[4];
    float* out = (float*)d_out;

    cudaMemsetAsync(out, 0, (size_t)out_size * sizeof(float));

    reset_kernel<<<1, 32>>>();
    gate_kernel<<<T_TOK, 128>>>((const float4*)x, (const float4*)gw1, gw2);
    if (out_size > T_TOK * DDIM) {
        loss_kernel<<<1, 1>>>(out + (size_t)T_TOK * DDIM);
    }

    {
        int n4w = (int)((size_t)NE * DDIM * (DDIM / 4));
        cvt_w_kernel<<<(n4w + 255) / 256, 256>>>((const float4*)ew);
    }

    int smem_bytes = (NSTAGE * (BM * ALD + BN * ALD) + BN + BM + BM) * (int)sizeof(float);
    cudaFuncSetAttribute(moe_gemm, cudaFuncAttributeMaxDynamicSharedMemorySize, smem_bytes);
    moe_gemm<<<dim3(T_TOK / BM, DDIM / BN, NE), GEMM_THREADS, smem_bytes>>>(eb, out);
}

// round 5
// speedup vs baseline: 1.0975x; 1.0975x over previous
#include <cuda_runtime.h>
#include <cstdint>

// Problem constants
#define T_TOK 4096      // total tokens (B*S)
#define DDIM  4096      // D_IN == D_OUT
#define NE    8         // experts

// GEMM tile config: CTA tile 128x128, 4 warps (2x2), warp tile 64x64
#define BM 128
#define BN 128
#define BK 32
#define NSTAGE 3
#define ALD 36          // BK + 4 pad (floats) -> conflict-free fragment LDS
#define GEMM_THREADS 128

// -------- device-global scratch (no allocation allowed) --------
__device__ int   g_cnt[NE];
__device__ float g_importance[NE];
__device__ int   g_tok[NE * T_TOK];
__device__ float g_scale[NE * T_TOK];
__device__ float g_xc[(size_t)T_TOK * DDIM];        // 64 MB  tf32-rounded x
__device__ float g_wc[(size_t)NE * DDIM * DDIM];    // 512 MB tf32-rounded W

// ---------------------------------------------------------------
__device__ __forceinline__ uint32_t f2tf(float f) {
    uint32_t r;
    asm volatile("cvt.rna.tf32.f32 %0, %1;\n" : "=r"(r) : "f"(f));
    return r;
}

__global__ void reset_kernel() {
    int i = threadIdx.x;
    if (i < NE) { g_cnt[i] = 0; g_importance[i] = 0.f; }
}

// One block (128 threads) per token: logits = tanh(x @ gw1^T) @ gw2^T, top-2,
// softmax, append to per-expert lists. Also writes tf32-rounded x to g_xc.
__global__ void gate_kernel(const float4* __restrict__ x4,
                            const float4* __restrict__ gw1_4,
                            const float* __restrict__ gw2) {
    int t = blockIdx.x;
    const float4* xr = x4 + (size_t)t * (DDIM / 4);
    float4* xc = (float4*)g_xc + (size_t)t * (DDIM / 4);

    float acc[NE];
#pragma unroll
    for (int e = 0; e < NE; e++) acc[e] = 0.f;

    for (int i = threadIdx.x; i < DDIM / 4; i += 128) {
        float4 v = xr[i];
        float4 r;
        r.x = __uint_as_float(f2tf(v.x));
        r.y = __uint_as_float(f2tf(v.y));
        r.z = __uint_as_float(f2tf(v.z));
        r.w = __uint_as_float(f2tf(v.w));
        xc[i] = r;
#pragma unroll
        for (int e = 0; e < NE; e++) {
            float4 w = gw1_4[e * (DDIM / 4) + i];
            acc[e] += v.x * w.x + v.y * w.y + v.z * w.z + v.w * w.w;
        }
    }
#pragma unroll
    for (int e = 0; e < NE; e++) {
#pragma unroll
        for (int o = 16; o > 0; o >>= 1)
            acc[e] += __shfl_xor_sync(0xffffffffu, acc[e], o);
    }
    __shared__ float part[NE][4];
    __shared__ float hs[NE];
    __shared__ float ls[NE];
    int lane = threadIdx.x & 31, warp = threadIdx.x >> 5;
    if (lane == 0) {
#pragma unroll
        for (int e = 0; e < NE; e++) part[e][warp] = acc[e];
    }
    __syncthreads();
    if (threadIdx.x < NE) {
        int e = threadIdx.x;
        hs[e] = tanhf(part[e][0] + part[e][1] + part[e][2] + part[e][3]);
    }
    __syncthreads();
    if (threadIdx.x < NE) {
        int j = threadIdx.x;
        float l = 0.f;
#pragma unroll
        for (int e = 0; e < NE; e++) l += gw2[j * NE + e] * hs[e];
        ls[j] = l;
    }
    __syncthreads();
    if (threadIdx.x == 0) {
        int i0 = 0; float v0 = ls[0];
        for (int j = 1; j < NE; j++) if (ls[j] > v0) { v0 = ls[j]; i0 = j; }
        int i1 = -1; float v1 = -3.4e38f;
        for (int j = 0; j < NE; j++) if (j != i0 && ls[j] > v1) { v1 = ls[j]; i1 = j; }
        float z  = expf(v1 - v0);
        float s0 = 1.f / (1.f + z);
        float s1 = z * s0;
        int p0 = atomicAdd(&g_cnt[i0], 1);
        g_tok[i0 * T_TOK + p0]   = t;
        g_scale[i0 * T_TOK + p0] = s0;
        int p1 = atomicAdd(&g_cnt[i1], 1);
        g_tok[i1 * T_TOK + p1]   = t;
        g_scale[i1 * T_TOK + p1] = s1;
        atomicAdd(&g_importance[i0], s0);
        atomicAdd(&g_importance[i1], s1);
    }
}

__global__ void loss_kernel(float* __restrict__ out) {
    float v[NE], w[NE];
    float m1 = 0.f, m2 = 0.f;
#pragma unroll
    for (int e = 0; e < NE; e++) {
        v[e] = g_importance[e];
        w[e] = (float)g_cnt[e];
        m1 += v[e]; m2 += w[e];
    }
    m1 *= (1.f / NE); m2 *= (1.f / NE);
    float var1 = 0.f, var2 = 0.f;
#pragma unroll
    for (int e = 0; e < NE; e++) {
        float d1 = v[e] - m1; var1 += d1 * d1;
        float d2 = w[e] - m2; var2 += d2 * d2;
    }
    var1 *= (1.f / (NE - 1)); var2 *= (1.f / (NE - 1));
    out[0] = 0.01f * (var1 / (m1 * m1 + 1e-10f) + var2 / (m2 * m2 + 1e-10f));
}

// ---------------- W pre-convert (rna fp32 -> tf32-precision fp32) ----------------
__global__ void cvt_w_kernel(const float4* __restrict__ src) {
    int i = blockIdx.x * 256 + threadIdx.x;
    const int n4 = (int)((size_t)NE * DDIM * (DDIM / 4));
    if (i < n4) {
        float4 v = src[i];
        v.x = __uint_as_float(f2tf(v.x));
        v.y = __uint_as_float(f2tf(v.y));
        v.z = __uint_as_float(f2tf(v.z));
        v.w = __uint_as_float(f2tf(v.w));
        ((float4*)g_wc)[i] = v;
    }
}

// ---------------------------------------------------------------
__device__ __forceinline__ void mma_tf32(float* c, const uint32_t* a, const uint32_t* b) {
    asm volatile(
        "mma.sync.aligned.m16n8k8.row.col.f32.tf32.tf32.f32 "
        "{%0,%1,%2,%3}, {%4,%5,%6,%7}, {%8,%9}, {%0,%1,%2,%3};\n"
        : "+f"(c[0]), "+f"(c[1]), "+f"(c[2]), "+f"(c[3])
        : "r"(a[0]), "r"(a[1]), "r"(a[2]), "r"(a[3]), "r"(b[0]), "r"(b[1]));
}
__device__ __forceinline__ void cp_async16(void* smem_dst, const void* gsrc) {
    uint32_t s = (uint32_t)__cvta_generic_to_shared(smem_dst);
    asm volatile("cp.async.cg.shared.global [%0], [%1], 16;\n" :: "r"(s), "l"(gsrc) : "memory");
}

// Grouped expert GEMM on tf32-rounded operands; epilogue scatter-add.
// CTA tile 128x128, 4 warps, warp tile 64x64 (2 warps along M, 2 along N).
__global__ void __launch_bounds__(GEMM_THREADS, 2)
moe_gemm(const float* __restrict__ bias, float* __restrict__ y) {
    int e   = blockIdx.z;
    int cnt = g_cnt[e];
    int m0  = blockIdx.x * BM;
    if (m0 >= cnt) return;
    int n0  = blockIdx.y * BN;

    extern __shared__ float smem[];
    float* As     = smem;                                   // NSTAGE*BM*ALD
    float* Bs     = As + NSTAGE * BM * ALD;                 // NSTAGE*BN*ALD
    float* sBias  = Bs + NSTAGE * BN * ALD;                 // BN
    float* sScale = sBias + BN;                             // BM
    int*   sTok   = (int*)(sScale + BM);                    // BM

    int tid = threadIdx.x;
    {
        int m = m0 + tid;
        bool valid = m < cnt;
        sTok[tid]   = valid ? g_tok[e * T_TOK + m]   : 0;
        sScale[tid] = valid ? g_scale[e * T_TOK + m] : 0.f;
        sBias[tid]  = bias[e * DDIM + n0 + tid];
    }
    __syncthreads();

    // per-thread load slots: 128 threads cover 16 rows x 8 chunk-cols per pass;
    // 8 passes for A (128 rows), 8 for B.
    int r_a = tid >> 3, c_a = tid & 7;      // r_a in 0..15, c_a in 0..7
    const float* a_src[8];
#pragma unroll
    for (int it = 0; it < 8; it++) {
        int r = r_a + it * 16;
        a_src[it] = g_xc + (size_t)sTok[r] * DDIM + c_a * 4;
    }
    const float* b_base = g_wc + ((size_t)e * DDIM + n0 + r_a) * DDIM + c_a * 4;

    auto load_stage = [&](int stage, int kt) {
        int kk = kt * BK;
        float* as = As + stage * (BM * ALD);
        float* bs = Bs + stage * (BN * ALD);
#pragma unroll
        for (int it = 0; it < 8; it++) {
            int r = r_a + it * 16;
            cp_async16(as + r * ALD + c_a * 4, a_src[it] + kk);
        }
#pragma unroll
        for (int it = 0; it < 8; it++) {
            int r = r_a + it * 16;
            cp_async16(bs + r * ALD + c_a * 4, b_base + (size_t)(it * 16) * DDIM + kk);
        }
        asm volatile("cp.async.commit_group;\n" ::: "memory");
    };

    const int KT = DDIM / BK;  // 128
    load_stage(0, 0);
    load_stage(1, 1);

    int warp = tid >> 5;        // 0..3
    int wm   = warp & 1;        // 2 warps along M -> 64 rows each
    int wn   = warp >> 1;       // 2 warps along N -> 64 cols each
    int lane = tid & 31;
    int gid  = lane >> 2;       // 0..7
    int tg   = lane & 3;        // 0..3

    float c[4][8][4];
#pragma unroll
    for (int mi = 0; mi < 4; mi++)
#pragma unroll
        for (int ni = 0; ni < 8; ni++)
#pragma unroll
            for (int j = 0; j < 4; j++) c[mi][ni][j] = 0.f;

    for (int i = 0; i < KT; i++) {
        if (i < KT - 1) {
            asm volatile("cp.async.wait_group 1;\n" ::: "memory");
        } else {
            asm volatile("cp.async.wait_group 0;\n" ::: "memory");
        }
        __syncthreads();
        if (i + 2 < KT) load_stage((i + 2) % NSTAGE, i + 2);

        const uint32_t* as = (const uint32_t*)(As + (i % NSTAGE) * (BM * ALD)) + (wm * 64) * ALD;
        const uint32_t* bs = (const uint32_t*)(Bs + (i % NSTAGE) * (BN * ALD)) + (wn * 64) * ALD;

#pragma unroll
        for (int ks = 0; ks < BK / 8; ks++) {
            uint32_t a[4][4], b[8][2];
#pragma unroll
            for (int mi = 0; mi < 4; mi++) {
                const uint32_t* ap = as + (mi * 16 + gid) * ALD + ks * 8 + tg;
                a[mi][0] = ap[0];
                a[mi][1] = ap[8 * ALD];
                a[mi][2] = ap[4];
                a[mi][3] = ap[8 * ALD + 4];
            }
#pragma unroll
            for (int ni = 0; ni < 8; ni++) {
                const uint32_t* bp = bs + (ni * 8 + gid) * ALD + ks * 8 + tg;
                b[ni][0] = bp[0];
                b[ni][1] = bp[4];
            }
#pragma unroll
            for (int mi = 0; mi < 4; mi++)
#pragma unroll
                for (int ni = 0; ni < 8; ni++)
                    mma_tf32(c[mi][ni], a[mi], b[ni]);
        }
    }

    // epilogue: scatter-add
#pragma unroll
    for (int mi = 0; mi < 4; mi++) {
#pragma unroll
        for (int half = 0; half < 2; half++) {
            int r = wm * 64 + mi * 16 + gid + half * 8;
            if (m0 + r >= cnt) continue;
            int   tok = sTok[r];
            float sc  = sScale[r];
            float* yr = y + (size_t)tok * DDIM + n0;
#pragma unroll
            for (int ni = 0; ni < 8; ni++) {
                int col = wn * 64 + ni * 8 + tg * 2;
                float v0 = sc * (c[mi][ni][half * 2 + 0] + sBias[col]);
                float v1 = sc * (c[mi][ni][half * 2 + 1] + sBias[col + 1]);
                atomicAdd(&yr[col],     v0);
                atomicAdd(&yr[col + 1], v1);
            }
        }
    }
}

// ---------------------------------------------------------------
extern "C" void kernel_launch(void* const* d_in, const int* in_sizes, int n_in,
                              void* d_out, int out_size) {
    const float* x   = (const float*)d_in[0];
    const float* gw1 = (const float*)d_in[1];
    const float* gw2 = (const float*)d_in[2];
    const float* ew  = (const float*)d_in[3];
    const float* eb  = (const float*)d_in[4];
    float* out = (float*)d_out;

    cudaMemsetAsync(out, 0, (size_t)out_size * sizeof(float));

    reset_kernel<<<1, 32>>>();
    gate_kernel<<<T_TOK, 128>>>((const float4*)x, (const float4*)gw1, gw2);
    if (out_size > T_TOK * DDIM) {
        loss_kernel<<<1, 1>>>(out + (size_t)T_TOK * DDIM);
    }

    {
        int n4w = (int)((size_t)NE * DDIM * (DDIM / 4));
        cvt_w_kernel<<<(n4w + 255) / 256, 256>>>((const float4*)ew);
    }

    int smem_bytes = (NSTAGE * (BM * ALD + BN * ALD) + BN + BM + BM) * (int)sizeof(float);
    cudaFuncSetAttribute(moe_gemm, cudaFuncAttributeMaxDynamicSharedMemorySize, smem_bytes);
    moe_gemm<<<dim3(T_TOK / BM, DDIM / BN, NE), GEMM_THREADS, smem_bytes>>>(eb, out);
}

// round 6
// speedup vs baseline: 1.8103x; 1.6494x over previous
#include <cuda_runtime.h>
#include <cuda_fp16.h>
#include <cstdint>

// Problem constants
#define T_TOK 4096      // total tokens (B*S)
#define DDIM  4096      // D_IN == D_OUT
#define NE    8         // experts

// GEMM tile config: CTA tile 128x128, 4 warps (2x2), warp tile 64x64, fp16 operands
#define BM 128
#define BN 128
#define BK 32           // halves per k-tile
#define NSTAGE 4
#define ALD_H 40        // halves per smem row (32 + 8 pad) -> conflict-free LDS
#define ALD_W 20        // uint32 words per smem row
#define GEMM_THREADS 128

// -------- device-global scratch (no allocation allowed) --------
__device__ int    g_cnt[NE];
__device__ float  g_importance[NE];
__device__ int    g_tok[NE * T_TOK];
__device__ float  g_scale[NE * T_TOK];
__device__ __half g_xh[(size_t)T_TOK * DDIM];        // 32 MB  fp16 x
__device__ __half g_wh[(size_t)NE * DDIM * DDIM];    // 256 MB fp16 W

// ---------------------------------------------------------------
__global__ void reset_kernel() {
    int i = threadIdx.x;
    if (i < NE) { g_cnt[i] = 0; g_importance[i] = 0.f; }
}

// One block (128 threads) per token: logits = tanh(x @ gw1^T) @ gw2^T, top-2,
// softmax, append to per-expert lists. Also writes fp16 x to g_xh.
__global__ void gate_kernel(const float4* __restrict__ x4,
                            const float4* __restrict__ gw1_4,
                            const float* __restrict__ gw2) {
    int t = blockIdx.x;
    const float4* xr = x4 + (size_t)t * (DDIM / 4);
    uint2* xc = (uint2*)(g_xh + (size_t)t * DDIM);

    float acc[NE];
#pragma unroll
    for (int e = 0; e < NE; e++) acc[e] = 0.f;

    for (int i = threadIdx.x; i < DDIM / 4; i += 128) {
        float4 v = xr[i];
        __half2 h0 = __floats2half2_rn(v.x, v.y);
        __half2 h1 = __floats2half2_rn(v.z, v.w);
        uint2 pk;
        pk.x = *(uint32_t*)&h0;
        pk.y = *(uint32_t*)&h1;
        xc[i] = pk;
#pragma unroll
        for (int e = 0; e < NE; e++) {
            float4 w = gw1_4[e * (DDIM / 4) + i];
            acc[e] += v.x * w.x + v.y * w.y + v.z * w.z + v.w * w.w;
        }
    }
#pragma unroll
    for (int e = 0; e < NE; e++) {
#pragma unroll
        for (int o = 16; o > 0; o >>= 1)
            acc[e] += __shfl_xor_sync(0xffffffffu, acc[e], o);
    }
    __shared__ float part[NE][4];
    __shared__ float hs[NE];
    __shared__ float ls[NE];
    int lane = threadIdx.x & 31, warp = threadIdx.x >> 5;
    if (lane == 0) {
#pragma unroll
        for (int e = 0; e < NE; e++) part[e][warp] = acc[e];
    }
    __syncthreads();
    if (threadIdx.x < NE) {
        int e = threadIdx.x;
        hs[e] = tanhf(part[e][0] + part[e][1] + part[e][2] + part[e][3]);
    }
    __syncthreads();
    if (threadIdx.x < NE) {
        int j = threadIdx.x;
        float l = 0.f;
#pragma unroll
        for (int e = 0; e < NE; e++) l += gw2[j * NE + e] * hs[e];
        ls[j] = l;
    }
    __syncthreads();
    if (threadIdx.x == 0) {
        int i0 = 0; float v0 = ls[0];
        for (int j = 1; j < NE; j++) if (ls[j] > v0) { v0 = ls[j]; i0 = j; }
        int i1 = -1; float v1 = -3.4e38f;
        for (int j = 0; j < NE; j++) if (j != i0 && ls[j] > v1) { v1 = ls[j]; i1 = j; }
        float z  = expf(v1 - v0);
        float s0 = 1.f / (1.f + z);
        float s1 = z * s0;
        int p0 = atomicAdd(&g_cnt[i0], 1);
        g_tok[i0 * T_TOK + p0]   = t;
        g_scale[i0 * T_TOK + p0] = s0;
        int p1 = atomicAdd(&g_cnt[i1], 1);
        g_tok[i1 * T_TOK + p1]   = t;
        g_scale[i1 * T_TOK + p1] = s1;
        atomicAdd(&g_importance[i0], s0);
        atomicAdd(&g_importance[i1], s1);
    }
}

__global__ void loss_kernel(float* __restrict__ out) {
    float v[NE], w[NE];
    float m1 = 0.f, m2 = 0.f;
#pragma unroll
    for (int e = 0; e < NE; e++) {
        v[e] = g_importance[e];
        w[e] = (float)g_cnt[e];
        m1 += v[e]; m2 += w[e];
    }
    m1 *= (1.f / NE); m2 *= (1.f / NE);
    float var1 = 0.f, var2 = 0.f;
#pragma unroll
    for (int e = 0; e < NE; e++) {
        float d1 = v[e] - m1; var1 += d1 * d1;
        float d2 = w[e] - m2; var2 += d2 * d2;
    }
    var1 *= (1.f / (NE - 1)); var2 *= (1.f / (NE - 1));
    out[0] = 0.01f * (var1 / (m1 * m1 + 1e-10f) + var2 / (m2 * m2 + 1e-10f));
}

// ---------------- W pre-convert (fp32 -> fp16 rn) ----------------
__global__ void cvt_w_kernel(const float4* __restrict__ src) {
    int i = blockIdx.x * 256 + threadIdx.x;
    const int n4 = (int)((size_t)NE * DDIM * (DDIM / 4));
    if (i < n4) {
        float4 v = src[i];
        __half2 h0 = __floats2half2_rn(v.x, v.y);
        __half2 h1 = __floats2half2_rn(v.z, v.w);
        uint2 pk;
        pk.x = *(uint32_t*)&h0;
        pk.y = *(uint32_t*)&h1;
        ((uint2*)g_wh)[i] = pk;
    }
}

// ---------------------------------------------------------------
__device__ __forceinline__ void mma_f16(float* c, const uint32_t* a, const uint32_t* b) {
    asm volatile(
        "mma.sync.aligned.m16n8k16.row.col.f32.f16.f16.f32 "
        "{%0,%1,%2,%3}, {%4,%5,%6,%7}, {%8,%9}, {%0,%1,%2,%3};\n"
        : "+f"(c[0]), "+f"(c[1]), "+f"(c[2]), "+f"(c[3])
        : "r"(a[0]), "r"(a[1]), "r"(a[2]), "r"(a[3]), "r"(b[0]), "r"(b[1]));
}
__device__ __forceinline__ void cp_async16(void* smem_dst, const void* gsrc) {
    uint32_t s = (uint32_t)__cvta_generic_to_shared(smem_dst);
    asm volatile("cp.async.cg.shared.global [%0], [%1], 16;\n" :: "r"(s), "l"(gsrc) : "memory");
}

// Grouped expert GEMM on fp16 operands (fp32 accumulate); epilogue scatter-add.
// CTA tile 128x128, 4 warps, warp tile 64x64 (2 warps along M, 2 along N).
__global__ void __launch_bounds__(GEMM_THREADS, 2)
moe_gemm(const float* __restrict__ bias, float* __restrict__ y) {
    int e   = blockIdx.z;
    int cnt = g_cnt[e];
    int m0  = blockIdx.x * BM;
    if (m0 >= cnt) return;
    int n0  = blockIdx.y * BN;

    extern __shared__ __half smh[];
    __half* Ash   = smh;                                   // NSTAGE*BM*ALD_H halves
    __half* Bsh   = Ash + NSTAGE * BM * ALD_H;             // NSTAGE*BN*ALD_H halves
    float* sBias  = (float*)(Bsh + NSTAGE * BN * ALD_H);   // BN
    float* sScale = sBias + BN;                            // BM
    int*   sTok   = (int*)(sScale + BM);                   // BM

    int tid = threadIdx.x;
    {
        int m = m0 + tid;
        bool valid = m < cnt;
        sTok[tid]   = valid ? g_tok[e * T_TOK + m]   : 0;
        sScale[tid] = valid ? g_scale[e * T_TOK + m] : 0.f;
        sBias[tid]  = bias[e * DDIM + n0 + tid];
    }
    __syncthreads();

    // loads: 128 threads cover 32 rows x 4 chunk-cols (16B = 8 halves) per pass; 4 passes.
    int r_a = tid >> 2, c_a = tid & 3;       // r_a in 0..31, c_a in 0..3
    const __half* a_src[4];
#pragma unroll
    for (int it = 0; it < 4; it++) {
        int r = r_a + it * 32;
        a_src[it] = g_xh + (size_t)sTok[r] * DDIM + c_a * 8;
    }
    const __half* b_base = g_wh + ((size_t)e * DDIM + n0 + r_a) * DDIM + c_a * 8;

    auto load_stage = [&](int stage, int kt) {
        int kk = kt * BK;
        __half* as = Ash + stage * (BM * ALD_H);
        __half* bs = Bsh + stage * (BN * ALD_H);
#pragma unroll
        for (int it = 0; it < 4; it++) {
            int r = r_a + it * 32;
            cp_async16(as + r * ALD_H + c_a * 8, a_src[it] + kk);
        }
#pragma unroll
        for (int it = 0; it < 4; it++) {
            int r = r_a + it * 32;
            cp_async16(bs + r * ALD_H + c_a * 8, b_base + (size_t)(it * 32) * DDIM + kk);
        }
        asm volatile("cp.async.commit_group;\n" ::: "memory");
    };

    const int KT = DDIM / BK;  // 128
    load_stage(0, 0);
    load_stage(1, 1);
    load_stage(2, 2);

    int warp = tid >> 5;        // 0..3
    int wm   = warp & 1;        // 2 warps along M -> 64 rows each
    int wn   = warp >> 1;       // 2 warps along N -> 64 cols each
    int lane = tid & 31;
    int gid  = lane >> 2;       // 0..7
    int tg   = lane & 3;        // 0..3

    float c[4][8][4];
#pragma unroll
    for (int mi = 0; mi < 4; mi++)
#pragma unroll
        for (int ni = 0; ni < 8; ni++)
#pragma unroll
            for (int j = 0; j < 4; j++) c[mi][ni][j] = 0.f;

    for (int i = 0; i < KT; i++) {
        if (i < KT - 2)       { asm volatile("cp.async.wait_group 2;\n" ::: "memory"); }
        else if (i == KT - 2) { asm volatile("cp.async.wait_group 1;\n" ::: "memory"); }
        else                  { asm volatile("cp.async.wait_group 0;\n" ::: "memory"); }
        __syncthreads();
        if (i + 3 < KT) load_stage((i + 3) % NSTAGE, i + 3);

        const uint32_t* as = (const uint32_t*)(Ash + (i % NSTAGE) * (BM * ALD_H)) + (wm * 64) * ALD_W;
        const uint32_t* bs = (const uint32_t*)(Bsh + (i % NSTAGE) * (BN * ALD_H)) + (wn * 64) * ALD_W;

#pragma unroll
        for (int ks = 0; ks < BK / 16; ks++) {           // 2 k16 steps
            uint32_t a[4][4], b[8][2];
#pragma unroll
            for (int mi = 0; mi < 4; mi++) {
                const uint32_t* ap = as + (mi * 16 + gid) * ALD_W + ks * 8 + tg;
                a[mi][0] = ap[0];
                a[mi][1] = ap[8 * ALD_W];
                a[mi][2] = ap[4];
                a[mi][3] = ap[8 * ALD_W + 4];
            }
#pragma unroll
            for (int ni = 0; ni < 8; ni++) {
                const uint32_t* bp = bs + (ni * 8 + gid) * ALD_W + ks * 8 + tg;
                b[ni][0] = bp[0];
                b[ni][1] = bp[4];
            }
#pragma unroll
            for (int mi = 0; mi < 4; mi++)
#pragma unroll
                for (int ni = 0; ni < 8; ni++)
                    mma_f16(c[mi][ni], a[mi], b[ni]);
        }
    }

    // epilogue: scatter-add
#pragma unroll
    for (int mi = 0; mi < 4; mi++) {
#pragma unroll
        for (int half = 0; half < 2; half++) {
            int r = wm * 64 + mi * 16 + gid + half * 8;
            if (m0 + r >= cnt) continue;
            int   tok = sTok[r];
            float sc  = sScale[r];
            float* yr = y + (size_t)tok * DDIM + n0;
#pragma unroll
            for (int ni = 0; ni < 8; ni++) {
                int col = wn * 64 + ni * 8 + tg * 2;
                float v0 = sc * (c[mi][ni][half * 2 + 0] + sBias[col]);
                float v1 = sc * (c[mi][ni][half * 2 + 1] + sBias[col + 1]);
                atomicAdd(&yr[col],     v0);
                atomicAdd(&yr[col + 1], v1);
            }
        }
    }
}

// ---------------------------------------------------------------
extern "C" void kernel_launch(void* const* d_in, const int* in_sizes, int n_in,
                              void* d_out, int out_size) {
    const float* x   = (const float*)d_in[0];
    const float* gw1 = (const float*)d_in[1];
    const float* gw2 = (const float*)d_in[2];
    const float* ew  = (const float*)d_in[3];
    const float* eb  = (const float*)d_in[4];
    float* out = (float*)d_out;

    cudaMemsetAsync(out, 0, (size_t)out_size * sizeof(float));

    reset_kernel<<<1, 32>>>();
    gate_kernel<<<T_TOK, 128>>>((const float4*)x, (const float4*)gw1, gw2);
    if (out_size > T_TOK * DDIM) {
        loss_kernel<<<1, 1>>>(out + (size_t)T_TOK * DDIM);
    }

    {
        int n4w = (int)((size_t)NE * DDIM * (DDIM / 4));
        cvt_w_kernel<<<(n4w + 255) / 256, 256>>>((const float4*)ew);
    }

    int smem_bytes = (NSTAGE * (BM * ALD_H + BN * ALD_H)) * 2 + (BN + BM + BM) * 4;
    cudaFuncSetAttribute(moe_gemm, cudaFuncAttributeMaxDynamicSharedMemorySize, smem_bytes);
    moe_gemm<<<dim3(T_TOK / BM, DDIM / BN, NE), GEMM_THREADS, smem_bytes>>>(eb, out);
}

// round 7
// speedup vs baseline: 2.0824x; 1.1503x over previous
#include <cuda_runtime.h>
#include <cuda_fp16.h>
#include <cstdint>

// Problem constants
#define T_TOK 4096      // total tokens (B*S)
#define DDIM  4096      // D_IN == D_OUT
#define NE    8         // experts

// GEMM tile config: CTA tile 128x128, 4 warps (2x2), warp tile 64x64, fp16 operands
#define BM 128
#define BN 128
#define BK 64           // halves per k-tile
#define NSTAGE 3
#define ALD_H 72        // halves per smem row (64 + 8 pad) -> conflict-free
#define GEMM_THREADS 128

// -------- device-global scratch (no allocation allowed) --------
__device__ int    g_cnt[NE];
__device__ float  g_importance[NE];
__device__ int    g_tok[NE * T_TOK];
__device__ float  g_scale[NE * T_TOK];
__device__ __half g_xh[(size_t)T_TOK * DDIM];        // 32 MB  fp16 x
__device__ __half g_wh[(size_t)NE * DDIM * DDIM];    // 256 MB fp16 W

// ---------------------------------------------------------------
__global__ void reset_kernel() {
    int i = threadIdx.x;
    if (i < NE) { g_cnt[i] = 0; g_importance[i] = 0.f; }
}

// One block (128 threads) per token: logits = tanh(x @ gw1^T) @ gw2^T, top-2,
// softmax, append to per-expert lists. Also writes fp16 x to g_xh.
__global__ void gate_kernel(const float4* __restrict__ x4,
                            const float4* __restrict__ gw1_4,
                            const float* __restrict__ gw2) {
    int t = blockIdx.x;
    const float4* xr = x4 + (size_t)t * (DDIM / 4);
    uint2* xc = (uint2*)(g_xh + (size_t)t * DDIM);

    float acc[NE];
#pragma unroll
    for (int e = 0; e < NE; e++) acc[e] = 0.f;

    for (int i = threadIdx.x; i < DDIM / 4; i += 128) {
        float4 v = xr[i];
        __half2 h0 = __floats2half2_rn(v.x, v.y);
        __half2 h1 = __floats2half2_rn(v.z, v.w);
        uint2 pk;
        pk.x = *(uint32_t*)&h0;
        pk.y = *(uint32_t*)&h1;
        xc[i] = pk;
#pragma unroll
        for (int e = 0; e < NE; e++) {
            float4 w = gw1_4[e * (DDIM / 4) + i];
            acc[e] += v.x * w.x + v.y * w.y + v.z * w.z + v.w * w.w;
        }
    }
#pragma unroll
    for (int e = 0; e < NE; e++) {
#pragma unroll
        for (int o = 16; o > 0; o >>= 1)
            acc[e] += __shfl_xor_sync(0xffffffffu, acc[e], o);
    }
    __shared__ float part[NE][4];
    __shared__ float hs[NE];
    __shared__ float ls[NE];
    int lane = threadIdx.x & 31, warp = threadIdx.x >> 5;
    if (lane == 0) {
#pragma unroll
        for (int e = 0; e < NE; e++) part[e][warp] = acc[e];
    }
    __syncthreads();
    if (threadIdx.x < NE) {
        int e = threadIdx.x;
        hs[e] = tanhf(part[e][0] + part[e][1] + part[e][2] + part[e][3]);
    }
    __syncthreads();
    if (threadIdx.x < NE) {
        int j = threadIdx.x;
        float l = 0.f;
#pragma unroll
        for (int e = 0; e < NE; e++) l += gw2[j * NE + e] * hs[e];
        ls[j] = l;
    }
    __syncthreads();
    if (threadIdx.x == 0) {
        int i0 = 0; float v0 = ls[0];
        for (int j = 1; j < NE; j++) if (ls[j] > v0) { v0 = ls[j]; i0 = j; }
        int i1 = -1; float v1 = -3.4e38f;
        for (int j = 0; j < NE; j++) if (j != i0 && ls[j] > v1) { v1 = ls[j]; i1 = j; }
        float z  = expf(v1 - v0);
        float s0 = 1.f / (1.f + z);
        float s1 = z * s0;
        int p0 = atomicAdd(&g_cnt[i0], 1);
        g_tok[i0 * T_TOK + p0]   = t;
        g_scale[i0 * T_TOK + p0] = s0;
        int p1 = atomicAdd(&g_cnt[i1], 1);
        g_tok[i1 * T_TOK + p1]   = t;
        g_scale[i1 * T_TOK + p1] = s1;
        atomicAdd(&g_importance[i0], s0);
        atomicAdd(&g_importance[i1], s1);
    }
}

__global__ void loss_kernel(float* __restrict__ out) {
    float v[NE], w[NE];
    float m1 = 0.f, m2 = 0.f;
#pragma unroll
    for (int e = 0; e < NE; e++) {
        v[e] = g_importance[e];
        w[e] = (float)g_cnt[e];
        m1 += v[e]; m2 += w[e];
    }
    m1 *= (1.f / NE); m2 *= (1.f / NE);
    float var1 = 0.f, var2 = 0.f;
#pragma unroll
    for (int e = 0; e < NE; e++) {
        float d1 = v[e] - m1; var1 += d1 * d1;
        float d2 = w[e] - m2; var2 += d2 * d2;
    }
    var1 *= (1.f / (NE - 1)); var2 *= (1.f / (NE - 1));
    out[0] = 0.01f * (var1 / (m1 * m1 + 1e-10f) + var2 / (m2 * m2 + 1e-10f));
}

// ---------------- W pre-convert (fp32 -> fp16 rn) ----------------
__global__ void cvt_w_kernel(const float4* __restrict__ src) {
    int i = blockIdx.x * 256 + threadIdx.x;
    const int n4 = (int)((size_t)NE * DDIM * (DDIM / 4));
    if (i < n4) {
        float4 v = src[i];
        __half2 h0 = __floats2half2_rn(v.x, v.y);
        __half2 h1 = __floats2half2_rn(v.z, v.w);
        uint2 pk;
        pk.x = *(uint32_t*)&h0;
        pk.y = *(uint32_t*)&h1;
        ((uint2*)g_wh)[i] = pk;
    }
}

// ---------------------------------------------------------------
__device__ __forceinline__ void mma_f16(float* c, const uint32_t* a, const uint32_t* b) {
    asm volatile(
        "mma.sync.aligned.m16n8k16.row.col.f32.f16.f16.f32 "
        "{%0,%1,%2,%3}, {%4,%5,%6,%7}, {%8,%9}, {%0,%1,%2,%3};\n"
        : "+f"(c[0]), "+f"(c[1]), "+f"(c[2]), "+f"(c[3])
        : "r"(a[0]), "r"(a[1]), "r"(a[2]), "r"(a[3]), "r"(b[0]), "r"(b[1]));
}
__device__ __forceinline__ void ldm_x4(uint32_t& r0, uint32_t& r1, uint32_t& r2, uint32_t& r3,
                                       uint32_t saddr) {
    asm volatile("ldmatrix.sync.aligned.m8n8.x4.shared.b16 {%0,%1,%2,%3}, [%4];\n"
                 : "=r"(r0), "=r"(r1), "=r"(r2), "=r"(r3) : "r"(saddr));
}
__device__ __forceinline__ void cp_async16(uint32_t saddr, const void* gsrc) {
    asm volatile("cp.async.cg.shared.global [%0], [%1], 16;\n" :: "r"(saddr), "l"(gsrc) : "memory");
}

// Grouped expert GEMM on fp16 operands (fp32 accumulate); epilogue scatter-add.
// CTA tile 128x128, 4 warps, warp tile 64x64; ldmatrix fragment loads; BK=64.
__global__ void __launch_bounds__(GEMM_THREADS, 2)
moe_gemm(const float* __restrict__ bias, float* __restrict__ y) {
    int e   = blockIdx.z;
    int cnt = g_cnt[e];
    int m0  = blockIdx.x * BM;
    if (m0 >= cnt) return;
    int n0  = blockIdx.y * BN;

    extern __shared__ __half smh[];
    __half* Ash   = smh;                                   // NSTAGE*BM*ALD_H halves
    __half* Bsh   = Ash + NSTAGE * BM * ALD_H;             // NSTAGE*BN*ALD_H halves
    float* sBias  = (float*)(Bsh + NSTAGE * BN * ALD_H);   // BN
    float* sScale = sBias + BN;                            // BM
    int*   sTok   = (int*)(sScale + BM);                   // BM

    uint32_t sb = (uint32_t)__cvta_generic_to_shared(smh);
    uint32_t aStage0 = sb;
    uint32_t bStage0 = sb + NSTAGE * BM * ALD_H * 2;

    int tid = threadIdx.x;
    {
        int m = m0 + tid;
        bool valid = m < cnt;
        sTok[tid]   = valid ? g_tok[e * T_TOK + m]   : 0;
        sScale[tid] = valid ? g_scale[e * T_TOK + m] : 0.f;
        sBias[tid]  = bias[e * DDIM + n0 + tid];
    }
    __syncthreads();

    // cp.async slots: 128 threads cover 16 rows x 8 chunk-cols (16B=8 halves); 8 row-passes.
    int r_ld = tid >> 3, c_ld = tid & 7;     // r_ld 0..15, c_ld 0..7
    const __half* a_src[8];
#pragma unroll
    for (int it = 0; it < 8; it++) {
        int r = r_ld + it * 16;
        a_src[it] = g_xh + (size_t)sTok[r] * DDIM + c_ld * 8;
    }
    const __half* b_base = g_wh + ((size_t)e * DDIM + n0 + r_ld) * DDIM + c_ld * 8;
    uint32_t stDstA = aStage0 + (r_ld * ALD_H + c_ld * 8) * 2;
    uint32_t stDstB = bStage0 + (r_ld * ALD_H + c_ld * 8) * 2;

    auto load_stage = [&](int stage, int kt) {
        int kk = kt * BK;
        uint32_t so = (uint32_t)(stage * (BM * ALD_H * 2));
#pragma unroll
        for (int it = 0; it < 8; it++) {
            cp_async16(stDstA + so + it * (16 * ALD_H * 2), a_src[it] + kk);
        }
#pragma unroll
        for (int it = 0; it < 8; it++) {
            cp_async16(stDstB + so + it * (16 * ALD_H * 2),
                       b_base + (size_t)(it * 16) * DDIM + kk);
        }
        asm volatile("cp.async.commit_group;\n" ::: "memory");
    };

    const int KT = DDIM / BK;  // 64
    load_stage(0, 0);
    load_stage(1, 1);

    int warp = tid >> 5;        // 0..3
    int wm   = warp & 1;        // 2 warps along M -> 64 rows each
    int wn   = warp >> 1;       // 2 warps along N -> 64 cols each
    int lane = tid & 31;
    int gid  = lane >> 2;       // 0..7
    int tg   = lane & 3;        // 0..3

    // ldmatrix per-thread address components (halves)
    int rA = ((lane >> 3) & 1) * 8 + (lane & 7);   // row within 16-row A tile
    int cA = ((lane >> 4) & 1) * 8;                // k-chunk within k16
    int rB = ((lane >> 4) & 1) * 8 + (lane & 7);   // row within 16-row B (n) tile
    int cB = ((lane >> 3) & 1) * 8;

    float c[4][8][4];
#pragma unroll
    for (int mi = 0; mi < 4; mi++)
#pragma unroll
        for (int ni = 0; ni < 8; ni++)
#pragma unroll
            for (int j = 0; j < 4; j++) c[mi][ni][j] = 0.f;

    for (int i = 0; i < KT; i++) {
        if (i < KT - 1) {
            asm volatile("cp.async.wait_group 1;\n" ::: "memory");
        } else {
            asm volatile("cp.async.wait_group 0;\n" ::: "memory");
        }
        __syncthreads();
        if (i + 2 < KT) load_stage((i + 2) % NSTAGE, i + 2);

        uint32_t aBase = aStage0 + (i % NSTAGE) * (BM * ALD_H * 2)
                       + ((wm * 64 + rA) * ALD_H + cA) * 2;
        uint32_t bBase = bStage0 + (i % NSTAGE) * (BN * ALD_H * 2)
                       + ((wn * 64 + rB) * ALD_H + cB) * 2;

#pragma unroll
        for (int ks = 0; ks < BK / 16; ks++) {           // 4 k16 steps
            uint32_t a[4][4], b[8][2];
#pragma unroll
            for (int mi = 0; mi < 4; mi++) {
                ldm_x4(a[mi][0], a[mi][1], a[mi][2], a[mi][3],
                       aBase + (mi * 16 * ALD_H + ks * 16) * 2);
            }
#pragma unroll
            for (int p = 0; p < 4; p++) {                // ni pairs
                ldm_x4(b[2 * p][0], b[2 * p][1], b[2 * p + 1][0], b[2 * p + 1][1],
                       bBase + (p * 16 * ALD_H + ks * 16) * 2);
            }
#pragma unroll
            for (int mi = 0; mi < 4; mi++)
#pragma unroll
                for (int ni = 0; ni < 8; ni++)
                    mma_f16(c[mi][ni], a[mi], b[ni]);
        }
    }

    // epilogue: scatter-add
#pragma unroll
    for (int mi = 0; mi < 4; mi++) {
#pragma unroll
        for (int half = 0; half < 2; half++) {
            int r = wm * 64 + mi * 16 + gid + half * 8;
            if (m0 + r >= cnt) continue;
            int   tok = sTok[r];
            float sc  = sScale[r];
            float* yr = y + (size_t)tok * DDIM + n0;
#pragma unroll
            for (int ni = 0; ni < 8; ni++) {
                int col = wn * 64 + ni * 8 + tg * 2;
                float v0 = sc * (c[mi][ni][half * 2 + 0] + sBias[col]);
                float v1 = sc * (c[mi][ni][half * 2 + 1] + sBias[col + 1]);
                atomicAdd(&yr[col],     v0);
                atomicAdd(&yr[col + 1], v1);
            }
        }
    }
}

// ---------------------------------------------------------------
extern "C" void kernel_launch(void* const* d_in, const int* in_sizes, int n_in,
                              void* d_out, int out_size) {
    const float* x   = (const float*)d_in[0];
    const float* gw1 = (const float*)d_in[1];
    const float* gw2 = (const float*)d_in[2];
    const float* ew  = (const float*)d_in[3];
    const float* eb  = (const float*)d_in[4];
    float* out = (float*)d_out;

    cudaMemsetAsync(out, 0, (size_t)out_size * sizeof(float));

    reset_kernel<<<1, 32>>>();
    gate_kernel<<<T_TOK, 128>>>((const float4*)x, (const float4*)gw1, gw2);
    if (out_size > T_TOK * DDIM) {
        loss_kernel<<<1, 1>>>(out + (size_t)T_TOK * DDIM);
    }

    {
        int n4w = (int)((size_t)NE * DDIM * (DDIM / 4));
        cvt_w_kernel<<<(n4w + 255) / 256, 256>>>((const float4*)ew);
    }

    int smem_bytes = (NSTAGE * (BM * ALD_H + BN * ALD_H)) * 2 + (BN + BM + BM) * 4;
    cudaFuncSetAttribute(moe_gemm, cudaFuncAttributeMaxDynamicSharedMemorySize, smem_bytes);
    moe_gemm<<<dim3(T_TOK / BM, DDIM / BN, NE), GEMM_THREADS, smem_bytes>>>(eb, out);
}